// round 6
// baseline (speedup 1.0000x reference)
#include <cuda_runtime.h>

// chamfer_3DDist: B=16, N=M=4096.
// Output (float32): [dist1 (B*N) | dist2 (B*M) | idx1 (B*N) | idx2 (B*M)]
//
// Round-6: symmetric single-pass. d(n,m) is bit-identical in both directions,
// so one pass over each (n,m) pair updates BOTH the row-min (dist1) and
// col-min (dist2) -> halves the fma-pipe work (the measured bottleneck).
// Candidates pre-scaled by -2 in smem: d = (-2*xy) + (q2+c2) rounds identically
// to the reference fma(-2, xy, q2+c2). Col partials: per-lane -> per-warp smem
// staging -> in-warp reduce every 8 units -> direct global store (no atomics).
// Finalize merges partials ascending and resolves exact first-occurrence
// indices via bit-identical rescans.

#define BT    64
#define UQ    4
#define QT    256            // queries per block (BT*UQ)
#define CT    1024           // candidates per block
#define NPTS  4096
#define BATCH 16
#define NQB   (NPTS / QT)    // 16 query blocks
#define NCB   (NPTS / CT)    // 4 cand blocks
#define GRPC  16             // row-deferral group (cands)
#define FLTMAX 3.402823466e38f

typedef unsigned long long u64;

// row partials: per cand-block: (best value, group index as float)
__device__ float2 g_row[NCB][BATCH * NPTS];
// col partials: per (query-block, warp): best value over that warp's 128 queries
__device__ float  g_col[NQB * 2][BATCH * NPTS];

__device__ __forceinline__ u64 pack2(float lo, float hi) {
    u64 r; asm("mov.b64 %0, {%1, %2};" : "=l"(r) : "f"(lo), "f"(hi)); return r;
}
__device__ __forceinline__ void unpack2(u64 v, float& lo, float& hi) {
    asm("mov.b64 {%0, %1}, %2;" : "=f"(lo), "=f"(hi) : "l"(v));
}
__device__ __forceinline__ u64 fma2(u64 a, u64 b, u64 c) {
    u64 d; asm("fma.rn.f32x2 %0, %1, %2, %3;" : "=l"(d) : "l"(a), "l"(b), "l"(c)); return d;
}
__device__ __forceinline__ u64 mul2(u64 a, u64 b) {
    u64 d; asm("mul.rn.f32x2 %0, %1, %2;" : "=l"(d) : "l"(a), "l"(b)); return d;
}
__device__ __forceinline__ u64 add2(u64 a, u64 b) {
    u64 d; asm("add.rn.f32x2 %0, %1, %2;" : "=l"(d) : "l"(a), "l"(b)); return d;
}

// Reference-rounded squared norm: ((x*x + y*y) + z*z), no contraction.
__device__ __forceinline__ float sqnorm_ref(float x, float y, float z) {
    return __fadd_rn(__fadd_rn(__fmul_rn(x, x), __fmul_rn(y, y)), __fmul_rn(z, z));
}
// Reference-rounded distance; q = xyz1 point, c = xyz2 point (operand order
// matches the main kernel).
__device__ __forceinline__ float dist_ref(float qx, float qy, float qz, float q2,
                                          float cx, float cy, float cz, float c2) {
    float xy = __fmaf_rn(qz, cz, __fmaf_rn(qy, cy, __fmul_rn(qx, cx)));
    return __fmaf_rn(-2.0f, xy, __fadd_rn(q2, c2));
}

__global__ __launch_bounds__(BT) void nn_main(
    const float* __restrict__ xyz1,
    const float* __restrict__ xyz2)
{
    const int cblk = blockIdx.x, qblk = blockIdx.y, b = blockIdx.z;
    const int tid = threadIdx.x, w = tid >> 5, lane = tid & 31;

    // cand tile: sc[pp][0]=(-2x0,-2x1,-2y0,-2y1)  sc[pp][1]=(-2z0,-2z1,w0,w1)
    __shared__ float4 sc[CT / 2][2];
    // per-warp col staging: [warp][pair 0..7][lane], stride 33 for bank spread
    __shared__ u64 colpart[2][8][33];

    // ---- stage candidates (xyz2 side), scaled by -2; norms from UNSCALED ----
    const float* cbase = xyz2 + (size_t)(b * NPTS + cblk * CT) * 3;
    for (int pp = tid; pp < CT / 2; pp += BT) {
        const float* p0 = cbase + 6 * pp;
        const float a0 = p0[0], a1 = p0[1], a2 = p0[2];
        const float b0 = p0[3], b1 = p0[4], b2 = p0[5];
        const float w0 = sqnorm_ref(a0, a1, a2);
        const float w1 = sqnorm_ref(b0, b1, b2);
        sc[pp][0] = make_float4(-2.0f * a0, -2.0f * b0, -2.0f * a1, -2.0f * b1);
        sc[pp][1] = make_float4(-2.0f * a2, -2.0f * b2, w0, w1);
    }

    // ---- queries (xyz1 side), packed broadcast ----
    u64 qx2[UQ], qy2[UQ], qz2[UQ], q22[UQ];
    float best[UQ], gacc[UQ], jgrp[UQ];
#pragma unroll
    for (int u = 0; u < UQ; ++u) {
        const int qi = b * NPTS + qblk * QT + u * BT + tid;
        const float* p = xyz1 + 3 * qi;
        const float x0 = p[0], x1 = p[1], x2v = p[2];
        const float s = sqnorm_ref(x0, x1, x2v);
        qx2[u] = pack2(x0, x0);
        qy2[u] = pack2(x1, x1);
        qz2[u] = pack2(x2v, x2v);
        q22[u] = pack2(s, s);
        best[u] = FLTMAX;
        gacc[u] = FLTMAX;
        jgrp[u] = 0.0f;
    }
    __syncthreads();

    const ulonglong2* __restrict__ sp = (const ulonglong2*)sc;
    float* __restrict__ gcol = &g_col[qblk * 2 + w][b * NPTS + cblk * CT];

    for (int k8 = 0; k8 < CT / 2; k8 += 8) {
#pragma unroll
        for (int j = 0; j < 8; ++j) {
            const int un = k8 + j;
            const ulonglong2 A  = sp[2 * un];      // (-2X pair, -2Y pair)
            const ulonglong2 Bv = sp[2 * un + 1];  // (-2Z pair,  W pair)
            float cl, ch;
#pragma unroll
            for (int u = 0; u < UQ; ++u) {
                // t = -2*xy exactly (scaling commutes with rounding here)
                u64 t = fma2(qz2[u], Bv.x, fma2(qy2[u], A.y, mul2(qx2[u], A.x)));
                u64 d = add2(t, add2(q22[u], Bv.y));   // == fma(-2,xy,q2+c2)
                float dlo, dhi; unpack2(d, dlo, dhi);
                gacc[u] = fminf(gacc[u], fminf(dlo, dhi));   // row path
                if (u == 0) { cl = dlo; ch = dhi; }
                else        { cl = fminf(cl, dlo); ch = fminf(ch, dhi); }
            }
            colpart[w][j][lane] = pack2(cl, ch);
        }

        // ---- row group commit (16 cands per group), ascending -> strict < ----
        const float gidx = (float)(cblk * (CT / GRPC) + (k8 >> 3));
#pragma unroll
        for (int u = 0; u < UQ; ++u) {
            jgrp[u] = (gacc[u] < best[u]) ? gidx : jgrp[u];   // SEL (pred-as-data)
            best[u] = fminf(best[u], gacc[u]);
            gacc[u] = FLTMAX;
        }

        // ---- col flush: 16 reductions (8 pairs x 2 lanes) over 32 lanes ----
        __syncwarp();
        {
            const int p = lane >> 2;          // pair 0..7
            const int s = (lane >> 1) & 1;    // which half of lanes to read
            const int h = lane & 1;           // lo/hi float of the u64
            const float* fb = (const float*)colpart[w][p];
            float v = fb[(s * 16) * 2 + h];
#pragma unroll
            for (int i = 1; i < 16; ++i)
                v = fminf(v, fb[(s * 16 + i) * 2 + h]);
            v = fminf(v, __shfl_xor_sync(0xffffffffu, v, 2));  // merge s halves
            if (!(lane & 2))
                gcol[k8 * 2 + p * 2 + h] = v;   // 16 writers, 16 consecutive cands
        }
        __syncwarp();
    }

    // ---- row epilogue ----
#pragma unroll
    for (int u = 0; u < UQ; ++u) {
        const int qg = b * NPTS + qblk * QT + u * BT + tid;
        g_row[cblk][qg] = make_float2(best[u], jgrp[u]);
    }
}

// Finalize: merge partials ascending (earliest wins ties) + bit-identical
// rescan for exact first-occurrence argmin indices.
__global__ __launch_bounds__(256) void nn_finalize(
    const float* __restrict__ xyz1,
    const float* __restrict__ xyz2,
    float* __restrict__ out)
{
    const int t = blockIdx.x * blockDim.x + threadIdx.x;   // [0, 2*BN)
    const int BN = BATCH * NPTS;

    if (t < BN) {
        // ---- row side: dist1/idx1 for query n of xyz1 ----
        const int qg = t;
        const int b  = qg / NPTS;
        const float* qp = xyz1 + 3 * qg;
        const float qx = qp[0], qy = qp[1], qz = qp[2];
        const float q2 = sqnorm_ref(qx, qy, qz);

        float2 r0 = g_row[0][qg];
        float bv = r0.x, bg = r0.y;
#pragma unroll
        for (int cb = 1; cb < NCB; ++cb) {
            const float2 r = g_row[cb][qg];
            const bool tk = r.x < bv;      // strict <: earliest cblk wins ties
            bv = tk ? r.x : bv;
            bg = tk ? r.y : bg;
        }
        const int base = (int)bg * GRPC;   // cand index within batch
        const float* cb3 = xyz2 + (size_t)b * NPTS * 3;
        int found = base;
#pragma unroll
        for (int k = GRPC - 1; k >= 0; --k) {   // descending: lowest match wins
            const float* cp = cb3 + 3 * (base + k);
            const float c2 = sqnorm_ref(cp[0], cp[1], cp[2]);
            const float d = dist_ref(qx, qy, qz, q2, cp[0], cp[1], cp[2], c2);
            if (d == bv) found = base + k;
        }
        out[qg]          = bv;              // dist1
        out[2 * BN + qg] = (float)found;    // idx1
    } else {
        // ---- col side: dist2/idx2 for cand m of xyz2 ----
        const int mg = t - BN;
        const int b  = mg / NPTS;
        const float* cp = xyz2 + 3 * mg;
        const float cx = cp[0], cy = cp[1], cz = cp[2];
        const float c2 = sqnorm_ref(cx, cy, cz);

        float bv = FLTMAX;
        int   bq = 0;
#pragma unroll
        for (int q = NQB - 1; q >= 0; --q) {   // descending + <= == ascending strict <
            const float v = fminf(g_col[2 * q][mg], g_col[2 * q + 1][mg]);
            if (v <= bv) { bv = v; bq = q; }   // keeps EARLIEST qblk on ties
        }
        // rescan the winning query block (256 queries) ascending
        const float* qb3 = xyz1 + (size_t)(b * NPTS + bq * QT) * 3;
        int found = bq * QT;
        for (int n = QT - 1; n >= 0; --n) {    // descending: lowest match wins
            const float* qp2 = qb3 + 3 * n;
            const float qxn = qp2[0], qyn = qp2[1], qzn = qp2[2];
            const float q2n = sqnorm_ref(qxn, qyn, qzn);
            const float d = dist_ref(qxn, qyn, qzn, q2n, cx, cy, cz, c2);
            if (d == bv) found = bq * QT + n;
        }
        out[BN + mg]     = bv;               // dist2
        out[3 * BN + mg] = (float)found;     // idx2
    }
}

extern "C" void kernel_launch(void* const* d_in, const int* in_sizes, int n_in,
                              void* d_out, int out_size)
{
    (void)in_sizes; (void)n_in; (void)out_size;
    const float* xyz1 = (const float*)d_in[0];
    const float* xyz2 = (const float*)d_in[1];
    float* out = (float*)d_out;

    dim3 grid(NCB, NQB, BATCH);   // (4, 16, 16) = 1024 blocks, one wave
    nn_main<<<grid, BT>>>(xyz1, xyz2);

    nn_finalize<<<(2 * BATCH * NPTS) / 256, 256>>>(xyz1, xyz2, out);
}

// round 7
// speedup vs baseline: 1.4215x; 1.4215x over previous
#include <cuda_runtime.h>

// chamfer_3DDist: B=16, N=M=4096.
// Output (float32): [dist1 (B*N) | dist2 (B*M) | idx1 (B*N) | idx2 (B*M)]
//
// Round-7: keep the symmetric single-pass main kernel (one pass updates both
// row-min and col-min; distances bit-identical to the reference). Rebuild the
// finalize stage: the round-6 col-side did a 256-iteration serial rescan per
// column (137us!). Now: one WARP per column — parallel 32-partial merge via
// shuffle butterfly (earliest qblk wins ties) + 8-iteration-per-lane rescan +
// shuffle-min over matching global indices (exact first-occurrence argmin).

#define BT    64
#define UQ    4
#define QT    256            // queries per block (BT*UQ)
#define CT    1024           // candidates per block
#define NPTS  4096
#define BATCH 16
#define NQB   (NPTS / QT)    // 16 query blocks
#define NCB   (NPTS / CT)    // 4 cand blocks
#define GRPC  16             // row-deferral group (cands)
#define FLTMAX 3.402823466e38f

typedef unsigned long long u64;

// row partials: per cand-block: (best value, group index as float)
__device__ float2 g_row[NCB][BATCH * NPTS];
// col partials: per (query-block, warp): best value over that warp's 128 queries
__device__ float  g_col[NQB * 2][BATCH * NPTS];

__device__ __forceinline__ u64 pack2(float lo, float hi) {
    u64 r; asm("mov.b64 %0, {%1, %2};" : "=l"(r) : "f"(lo), "f"(hi)); return r;
}
__device__ __forceinline__ void unpack2(u64 v, float& lo, float& hi) {
    asm("mov.b64 {%0, %1}, %2;" : "=f"(lo), "=f"(hi) : "l"(v));
}
__device__ __forceinline__ u64 fma2(u64 a, u64 b, u64 c) {
    u64 d; asm("fma.rn.f32x2 %0, %1, %2, %3;" : "=l"(d) : "l"(a), "l"(b), "l"(c)); return d;
}
__device__ __forceinline__ u64 mul2(u64 a, u64 b) {
    u64 d; asm("mul.rn.f32x2 %0, %1, %2;" : "=l"(d) : "l"(a), "l"(b)); return d;
}
__device__ __forceinline__ u64 add2(u64 a, u64 b) {
    u64 d; asm("add.rn.f32x2 %0, %1, %2;" : "=l"(d) : "l"(a), "l"(b)); return d;
}

// Reference-rounded squared norm: ((x*x + y*y) + z*z), no contraction.
__device__ __forceinline__ float sqnorm_ref(float x, float y, float z) {
    return __fadd_rn(__fadd_rn(__fmul_rn(x, x), __fmul_rn(y, y)), __fmul_rn(z, z));
}
// Reference-rounded distance; q = xyz1 point, c = xyz2 point.
__device__ __forceinline__ float dist_ref(float qx, float qy, float qz, float q2,
                                          float cx, float cy, float cz, float c2) {
    float xy = __fmaf_rn(qz, cz, __fmaf_rn(qy, cy, __fmul_rn(qx, cx)));
    return __fmaf_rn(-2.0f, xy, __fadd_rn(q2, c2));
}

__global__ __launch_bounds__(BT) void nn_main(
    const float* __restrict__ xyz1,
    const float* __restrict__ xyz2)
{
    const int cblk = blockIdx.x, qblk = blockIdx.y, b = blockIdx.z;
    const int tid = threadIdx.x, w = tid >> 5, lane = tid & 31;

    __shared__ float4 sc[CT / 2][2];
    __shared__ u64 colpart[2][8][33];

    // stage candidates (xyz2 side), scaled by -2; norms from UNSCALED coords
    const float* cbase = xyz2 + (size_t)(b * NPTS + cblk * CT) * 3;
    for (int pp = tid; pp < CT / 2; pp += BT) {
        const float* p0 = cbase + 6 * pp;
        const float a0 = p0[0], a1 = p0[1], a2 = p0[2];
        const float b0 = p0[3], b1 = p0[4], b2 = p0[5];
        const float w0 = sqnorm_ref(a0, a1, a2);
        const float w1 = sqnorm_ref(b0, b1, b2);
        sc[pp][0] = make_float4(-2.0f * a0, -2.0f * b0, -2.0f * a1, -2.0f * b1);
        sc[pp][1] = make_float4(-2.0f * a2, -2.0f * b2, w0, w1);
    }

    u64 qx2[UQ], qy2[UQ], qz2[UQ], q22[UQ];
    float best[UQ], gacc[UQ], jgrp[UQ];
#pragma unroll
    for (int u = 0; u < UQ; ++u) {
        const int qi = b * NPTS + qblk * QT + u * BT + tid;
        const float* p = xyz1 + 3 * qi;
        const float x0 = p[0], x1 = p[1], x2v = p[2];
        const float s = sqnorm_ref(x0, x1, x2v);
        qx2[u] = pack2(x0, x0);
        qy2[u] = pack2(x1, x1);
        qz2[u] = pack2(x2v, x2v);
        q22[u] = pack2(s, s);
        best[u] = FLTMAX;
        gacc[u] = FLTMAX;
        jgrp[u] = 0.0f;
    }
    __syncthreads();

    const ulonglong2* __restrict__ sp = (const ulonglong2*)sc;
    float* __restrict__ gcol = &g_col[qblk * 2 + w][b * NPTS + cblk * CT];

    for (int k8 = 0; k8 < CT / 2; k8 += 8) {
#pragma unroll
        for (int j = 0; j < 8; ++j) {
            const int un = k8 + j;
            const ulonglong2 A  = sp[2 * un];      // (-2X pair, -2Y pair)
            const ulonglong2 Bv = sp[2 * un + 1];  // (-2Z pair,  W pair)
            float cl, ch;
#pragma unroll
            for (int u = 0; u < UQ; ++u) {
                u64 t = fma2(qz2[u], Bv.x, fma2(qy2[u], A.y, mul2(qx2[u], A.x)));
                u64 d = add2(t, add2(q22[u], Bv.y));   // == fma(-2,xy,q2+c2)
                float dlo, dhi; unpack2(d, dlo, dhi);
                gacc[u] = fminf(gacc[u], fminf(dlo, dhi));
                if (u == 0) { cl = dlo; ch = dhi; }
                else        { cl = fminf(cl, dlo); ch = fminf(ch, dhi); }
            }
            colpart[w][j][lane] = pack2(cl, ch);
        }

        // row group commit (16 cands per group), ascending -> strict <
        const float gidx = (float)(cblk * (CT / GRPC) + (k8 >> 3));
#pragma unroll
        for (int u = 0; u < UQ; ++u) {
            jgrp[u] = (gacc[u] < best[u]) ? gidx : jgrp[u];
            best[u] = fminf(best[u], gacc[u]);
            gacc[u] = FLTMAX;
        }

        // col flush: 16 reductions (8 pairs x 2 halves) over 32 lanes
        __syncwarp();
        {
            const int p = lane >> 2;
            const int s = (lane >> 1) & 1;
            const int h = lane & 1;
            const float* fb = (const float*)colpart[w][p];
            float v = fb[(s * 16) * 2 + h];
#pragma unroll
            for (int i = 1; i < 16; ++i)
                v = fminf(v, fb[(s * 16 + i) * 2 + h]);
            v = fminf(v, __shfl_xor_sync(0xffffffffu, v, 2));
            if (!(lane & 2))
                gcol[k8 * 2 + p * 2 + h] = v;
        }
        __syncwarp();
    }

#pragma unroll
    for (int u = 0; u < UQ; ++u) {
        const int qg = b * NPTS + qblk * QT + u * BT + tid;
        g_row[cblk][qg] = make_float2(best[u], jgrp[u]);
    }
}

// Row finalize: thread per query. Merge NCB partials ascending, rescan the
// winning 16-cand group bit-identically (descending overwrite -> lowest wins).
__global__ __launch_bounds__(256) void nn_fin_row(
    const float* __restrict__ xyz1,
    const float* __restrict__ xyz2,
    float* __restrict__ out)
{
    const int qg = blockIdx.x * blockDim.x + threadIdx.x;   // [0, BN)
    const int BN = BATCH * NPTS;
    const int b  = qg / NPTS;

    const float* qp = xyz1 + 3 * qg;
    const float qx = qp[0], qy = qp[1], qz = qp[2];
    const float q2 = sqnorm_ref(qx, qy, qz);

    float2 r0 = g_row[0][qg];
    float bv = r0.x, bg = r0.y;
#pragma unroll
    for (int cb = 1; cb < NCB; ++cb) {
        const float2 r = g_row[cb][qg];
        const bool tk = r.x < bv;
        bv = tk ? r.x : bv;
        bg = tk ? r.y : bg;
    }
    const int base = (int)bg * GRPC;
    const float* cb3 = xyz2 + (size_t)b * NPTS * 3;
    int found = base;
#pragma unroll
    for (int k = GRPC - 1; k >= 0; --k) {
        const float* cp = cb3 + 3 * (base + k);
        const float c2 = sqnorm_ref(cp[0], cp[1], cp[2]);
        const float d = dist_ref(qx, qy, qz, q2, cp[0], cp[1], cp[2], c2);
        if (d == bv) found = base + k;
    }
    out[qg]          = bv;
    out[2 * BN + qg] = (float)found;
}

// Col finalize: one WARP per column m. Lane l merges partial l; shuffle
// butterfly picks (min value, earliest qblk). Rescan of the winning 256-query
// block is split 8 queries/lane; shuffle-min over matching global indices
// gives the exact first-occurrence argmin.
__global__ __launch_bounds__(256) void nn_fin_col(
    const float* __restrict__ xyz1,
    const float* __restrict__ xyz2,
    float* __restrict__ out)
{
    const int BN   = BATCH * NPTS;
    const int wid  = (blockIdx.x * blockDim.x + threadIdx.x) >> 5;  // column id
    const int lane = threadIdx.x & 31;
    const int mg   = wid;              // [0, BN)
    const int b    = mg / NPTS;

    // merge 32 partials: lane l owns g_col[l][mg]; key = (value, qblk=l>>1)
    float v = g_col[lane][mg];
    int   q = lane >> 1;
#pragma unroll
    for (int off = 16; off >= 1; off >>= 1) {
        const float ov = __shfl_xor_sync(0xffffffffu, v, off);
        const int   oq = __shfl_xor_sync(0xffffffffu, q, off);
        const bool tk = (ov < v) || (ov == v && oq < q);
        v = tk ? ov : v;
        q = tk ? oq : q;
    }
    // all lanes now hold bv = min value, bq = earliest tying qblk
    const float bv = v;
    const int   bq = q;

    const float* cp = xyz2 + 3 * mg;
    const float cx = cp[0], cy = cp[1], cz = cp[2];
    const float c2 = sqnorm_ref(cx, cy, cz);

    // rescan: lane l handles queries [bq*QT + l*8, +8), descending overwrite
    const float* qb3 = xyz1 + (size_t)(b * NPTS + bq * QT) * 3;
    int found = 0x7fffffff;
#pragma unroll
    for (int k = 7; k >= 0; --k) {
        const int n = lane * 8 + k;
        const float* qp2 = qb3 + 3 * n;
        const float qxn = qp2[0], qyn = qp2[1], qzn = qp2[2];
        const float q2n = sqnorm_ref(qxn, qyn, qzn);
        const float d = dist_ref(qxn, qyn, qzn, q2n, cx, cy, cz, c2);
        if (d == bv) found = bq * QT + n;
    }
#pragma unroll
    for (int off = 16; off >= 1; off >>= 1)
        found = min(found, __shfl_xor_sync(0xffffffffu, found, off));

    if (lane == 0) {
        out[BN + mg]     = bv;
        out[3 * BN + mg] = (float)found;
    }
}

extern "C" void kernel_launch(void* const* d_in, const int* in_sizes, int n_in,
                              void* d_out, int out_size)
{
    (void)in_sizes; (void)n_in; (void)out_size;
    const float* xyz1 = (const float*)d_in[0];
    const float* xyz2 = (const float*)d_in[1];
    float* out = (float*)d_out;

    dim3 grid(NCB, NQB, BATCH);   // (4, 16, 16) = 1024 blocks, one wave
    nn_main<<<grid, BT>>>(xyz1, xyz2);

    const int BN = BATCH * NPTS;
    nn_fin_row<<<BN / 256, 256>>>(xyz1, xyz2, out);
    nn_fin_col<<<(BN * 32) / 256, 256>>>(xyz1, xyz2, out);
}

// round 8
// speedup vs baseline: 2.1629x; 1.5216x over previous
#include <cuda_runtime.h>

// chamfer_3DDist: B=16, N=M=4096.
// Output (float32): [dist1 (B*N) | dist2 (B*M) | idx1 (B*N) | idx2 (B*M)]
//
// Round-8: symmetric single-pass main kernel (each (n,m) pair computed once,
// updating both row-min and col-min; distances bit-identical to reference).
// Changes vs R7:
//  (1) threads own CONTIGUOUS query quads -> each warp's col partial covers a
//      contiguous 128-query range; tie-break by earliest partial is exact.
//  (2) finalize col rescan is fully coalesced (3x float4 per lane over the
//      winning 128-query range) and only 128 queries.
//  (3) CT=512 doubles the block count for occupancy (20 warps/SM resident).

#define BT    64
#define UQ    4
#define QT    256            // queries per block (BT*UQ)
#define CT    512            // candidates per block
#define NPTS  4096
#define BATCH 16
#define NQB   (NPTS / QT)    // 16
#define NCB   (NPTS / CT)    // 8
#define GRPC  16             // row-deferral group (cands)
#define NPART (NQB * 2)      // 32 col partials, each a contiguous 128-query range
#define FLTMAX 3.402823466e38f

typedef unsigned long long u64;

// row partials: per cand-block: (best value, group index as float)
__device__ float2 g_row[NCB][BATCH * NPTS];
// col partials: partial p covers queries [p*128, p*128+128) within the batch
__device__ float  g_col[NPART][BATCH * NPTS];

__device__ __forceinline__ u64 pack2(float lo, float hi) {
    u64 r; asm("mov.b64 %0, {%1, %2};" : "=l"(r) : "f"(lo), "f"(hi)); return r;
}
__device__ __forceinline__ void unpack2(u64 v, float& lo, float& hi) {
    asm("mov.b64 {%0, %1}, %2;" : "=f"(lo), "=f"(hi) : "l"(v));
}
__device__ __forceinline__ u64 fma2(u64 a, u64 b, u64 c) {
    u64 d; asm("fma.rn.f32x2 %0, %1, %2, %3;" : "=l"(d) : "l"(a), "l"(b), "l"(c)); return d;
}
__device__ __forceinline__ u64 mul2(u64 a, u64 b) {
    u64 d; asm("mul.rn.f32x2 %0, %1, %2;" : "=l"(d) : "l"(a), "l"(b)); return d;
}
__device__ __forceinline__ u64 add2(u64 a, u64 b) {
    u64 d; asm("add.rn.f32x2 %0, %1, %2;" : "=l"(d) : "l"(a), "l"(b)); return d;
}

__device__ __forceinline__ float sqnorm_ref(float x, float y, float z) {
    return __fadd_rn(__fadd_rn(__fmul_rn(x, x), __fmul_rn(y, y)), __fmul_rn(z, z));
}
__device__ __forceinline__ float dist_ref(float qx, float qy, float qz, float q2,
                                          float cx, float cy, float cz, float c2) {
    float xy = __fmaf_rn(qz, cz, __fmaf_rn(qy, cy, __fmul_rn(qx, cx)));
    return __fmaf_rn(-2.0f, xy, __fadd_rn(q2, c2));
}

__global__ __launch_bounds__(BT) void nn_main(
    const float* __restrict__ xyz1,
    const float* __restrict__ xyz2)
{
    const int cblk = blockIdx.x, qblk = blockIdx.y, b = blockIdx.z;
    const int tid = threadIdx.x, w = tid >> 5, lane = tid & 31;

    __shared__ float4 sc[CT / 2][2];
    __shared__ u64 colpart[2][8][33];
    __shared__ float2 rowst[QT];

    // stage candidates (xyz2), scaled by -2; norms from UNSCALED coords
    const float* cbase = xyz2 + (size_t)(b * NPTS + cblk * CT) * 3;
    for (int pp = tid; pp < CT / 2; pp += BT) {
        const float* p0 = cbase + 6 * pp;
        const float a0 = p0[0], a1 = p0[1], a2 = p0[2];
        const float b0 = p0[3], b1 = p0[4], b2 = p0[5];
        const float w0 = sqnorm_ref(a0, a1, a2);
        const float w1 = sqnorm_ref(b0, b1, b2);
        sc[pp][0] = make_float4(-2.0f * a0, -2.0f * b0, -2.0f * a1, -2.0f * b1);
        sc[pp][1] = make_float4(-2.0f * a2, -2.0f * b2, w0, w1);
    }

    // queries: thread owns 4 CONSECUTIVE queries (12 contiguous floats)
    u64 qx2[UQ], qy2[UQ], qz2[UQ], q22[UQ];
    float best[UQ], gacc[UQ], jgrp[UQ];
    {
        const int q0 = b * NPTS + qblk * QT + tid * UQ;
        const float4* qv = (const float4*)(xyz1 + 3 * q0);
        const float4 v0 = qv[0], v1 = qv[1], v2 = qv[2];
        const float qs[UQ][3] = {{v0.x, v0.y, v0.z}, {v0.w, v1.x, v1.y},
                                 {v1.z, v1.w, v2.x}, {v2.y, v2.z, v2.w}};
#pragma unroll
        for (int u = 0; u < UQ; ++u) {
            const float x0 = qs[u][0], x1 = qs[u][1], x2v = qs[u][2];
            const float s = sqnorm_ref(x0, x1, x2v);
            qx2[u] = pack2(x0, x0);
            qy2[u] = pack2(x1, x1);
            qz2[u] = pack2(x2v, x2v);
            q22[u] = pack2(s, s);
            best[u] = FLTMAX;
            gacc[u] = FLTMAX;
            jgrp[u] = 0.0f;
        }
    }
    __syncthreads();

    const ulonglong2* __restrict__ sp = (const ulonglong2*)sc;
    float* __restrict__ gcol = &g_col[qblk * 2 + w][b * NPTS + cblk * CT];

    for (int k8 = 0; k8 < CT / 2; k8 += 8) {
#pragma unroll
        for (int j = 0; j < 8; ++j) {
            const int un = k8 + j;
            const ulonglong2 A  = sp[2 * un];      // (-2X pair, -2Y pair)
            const ulonglong2 Bv = sp[2 * un + 1];  // (-2Z pair,  W pair)
            float cl, ch;
#pragma unroll
            for (int u = 0; u < UQ; ++u) {
                u64 t = fma2(qz2[u], Bv.x, fma2(qy2[u], A.y, mul2(qx2[u], A.x)));
                u64 d = add2(t, add2(q22[u], Bv.y));   // == fma(-2,xy,q2+c2)
                float dlo, dhi; unpack2(d, dlo, dhi);
                gacc[u] = fminf(gacc[u], fminf(dlo, dhi));
                if (u == 0) { cl = dlo; ch = dhi; }
                else        { cl = fminf(cl, dlo); ch = fminf(ch, dhi); }
            }
            colpart[w][j][lane] = pack2(cl, ch);
        }

        // row group commit (16 cands/group), ascending -> strict <
        const float gidx = (float)(cblk * (CT / GRPC) + (k8 >> 3));
#pragma unroll
        for (int u = 0; u < UQ; ++u) {
            jgrp[u] = (gacc[u] < best[u]) ? gidx : jgrp[u];
            best[u] = fminf(best[u], gacc[u]);
            gacc[u] = FLTMAX;
        }

        // col flush: 16 reductions (8 pairs x 2 halves) over 32 lanes
        __syncwarp();
        {
            const int p = lane >> 2;
            const int s = (lane >> 1) & 1;
            const int h = lane & 1;
            const float* fb = (const float*)colpart[w][p];
            float v = fb[(s * 16) * 2 + h];
#pragma unroll
            for (int i = 1; i < 16; ++i)
                v = fminf(v, fb[(s * 16 + i) * 2 + h]);
            v = fminf(v, __shfl_xor_sync(0xffffffffu, v, 2));
            if (!(lane & 2))
                gcol[k8 * 2 + p * 2 + h] = v;
        }
        __syncwarp();
    }

    // row epilogue: stage to smem, write coalesced
#pragma unroll
    for (int u = 0; u < UQ; ++u)
        rowst[tid * UQ + u] = make_float2(best[u], jgrp[u]);
    __syncthreads();
    {
        const int base = b * NPTS + qblk * QT;
        float2* __restrict__ gr = &g_row[cblk][base];
        for (int i = tid; i < QT; i += BT) gr[i] = rowst[i];
    }
}

// Row finalize: thread per query. Merge NCB partials ascending, rescan the
// winning 16-cand group bit-identically (descending overwrite -> lowest wins).
__global__ __launch_bounds__(256) void nn_fin_row(
    const float* __restrict__ xyz1,
    const float* __restrict__ xyz2,
    float* __restrict__ out)
{
    const int qg = blockIdx.x * blockDim.x + threadIdx.x;   // [0, BN)
    const int BN = BATCH * NPTS;
    const int b  = qg / NPTS;

    const float* qp = xyz1 + 3 * qg;
    const float qx = qp[0], qy = qp[1], qz = qp[2];
    const float q2 = sqnorm_ref(qx, qy, qz);

    float2 r0 = g_row[0][qg];
    float bv = r0.x, bg = r0.y;
#pragma unroll
    for (int cb = 1; cb < NCB; ++cb) {
        const float2 r = g_row[cb][qg];
        const bool tk = r.x < bv;
        bv = tk ? r.x : bv;
        bg = tk ? r.y : bg;
    }
    const int base = (int)bg * GRPC;
    const float* cb3 = xyz2 + (size_t)b * NPTS * 3;
    int found = base;
#pragma unroll
    for (int k = GRPC - 1; k >= 0; --k) {
        const float* cp = cb3 + 3 * (base + k);
        const float c2 = sqnorm_ref(cp[0], cp[1], cp[2]);
        const float d = dist_ref(qx, qy, qz, q2, cp[0], cp[1], cp[2], c2);
        if (d == bv) found = base + k;
    }
    out[qg]          = bv;
    out[2 * BN + qg] = (float)found;
}

// Col finalize: one WARP per column m. Lane l merges partial l (contiguous
// 128-query range [l*128, l*128+128)); butterfly keeps (min value, earliest
// range). Rescan: lane l recomputes its 4 CONSECUTIVE queries (coalesced
// float4 loads) of the winning range; shuffle-min over matching global
// indices -> exact first-occurrence argmin.
__global__ __launch_bounds__(256) void nn_fin_col(
    const float* __restrict__ xyz1,
    const float* __restrict__ xyz2,
    float* __restrict__ out)
{
    const int BN   = BATCH * NPTS;
    const int mg   = (blockIdx.x * blockDim.x + threadIdx.x) >> 5;  // column
    const int lane = threadIdx.x & 31;
    const int b    = mg / NPTS;

    // merge 32 contiguous-range partials: earliest range wins ties
    float v = g_col[lane][mg];
    int   p = lane;
#pragma unroll
    for (int off = 16; off >= 1; off >>= 1) {
        const float ov = __shfl_xor_sync(0xffffffffu, v, off);
        const int   op = __shfl_xor_sync(0xffffffffu, p, off);
        const bool tk = (ov < v) || (ov == v && op < p);
        v = tk ? ov : v;
        p = tk ? op : p;
    }
    const float bv = v;
    const int   bp = p;     // winning partial: queries [bp*128, bp*128+128)

    const float* cp = xyz2 + 3 * mg;
    const float cx = cp[0], cy = cp[1], cz = cp[2];
    const float c2 = sqnorm_ref(cx, cy, cz);

    // rescan: lane l -> queries bp*128 + l*4 + {0..3}, fully coalesced
    const int q0 = b * NPTS + bp * 128 + lane * 4;
    const float4* qv = (const float4*)(xyz1 + 3 * q0);
    const float4 v0 = qv[0], v1 = qv[1], v2 = qv[2];
    const float qs[4][3] = {{v0.x, v0.y, v0.z}, {v0.w, v1.x, v1.y},
                            {v1.z, v1.w, v2.x}, {v2.y, v2.z, v2.w}};
    int found = 0x7fffffff;
#pragma unroll
    for (int k = 3; k >= 0; --k) {
        const float q2n = sqnorm_ref(qs[k][0], qs[k][1], qs[k][2]);
        const float d = dist_ref(qs[k][0], qs[k][1], qs[k][2], q2n, cx, cy, cz, c2);
        if (d == bv) found = bp * 128 + lane * 4 + k;
    }
#pragma unroll
    for (int off = 16; off >= 1; off >>= 1)
        found = min(found, __shfl_xor_sync(0xffffffffu, found, off));

    if (lane == 0) {
        out[BN + mg]     = bv;
        out[3 * BN + mg] = (float)found;
    }
}

extern "C" void kernel_launch(void* const* d_in, const int* in_sizes, int n_in,
                              void* d_out, int out_size)
{
    (void)in_sizes; (void)n_in; (void)out_size;
    const float* xyz1 = (const float*)d_in[0];
    const float* xyz2 = (const float*)d_in[1];
    float* out = (float*)d_out;

    dim3 grid(NCB, NQB, BATCH);   // (8, 16, 16) = 2048 blocks
    nn_main<<<grid, BT>>>(xyz1, xyz2);

    const int BN = BATCH * NPTS;
    nn_fin_row<<<BN / 256, 256>>>(xyz1, xyz2, out);
    nn_fin_col<<<(BN * 32) / 256, 256>>>(xyz1, xyz2, out);
}

// round 9
// speedup vs baseline: 2.3023x; 1.0644x over previous
#include <cuda_runtime.h>

// chamfer_3DDist: B=16, N=M=4096.
// Output (float32): [dist1 (B*N) | dist2 (B*M) | idx1 (B*N) | idx2 (B*M)]
//
// Round-9: (1) CT=256 -> 4096 main blocks, 32 resident warps/SM (8/SMSP) to
// lift issue% (was 53.6 at 20 warps/SM); (2) single fused finalize kernel,
// warp-parallel for BOTH rows and cols (R8's thread-per-query row finalize was
// serial/latency-bound). Distances everywhere bit-identical to the reference:
// d = (-2*xy chain) + (q2 + c2), scaling by -2 commutes with rounding.

#define BT    64
#define UQ    4
#define QT    256            // queries per block (BT*UQ)
#define CT    256            // candidates per block
#define NPTS  4096
#define BATCH 16
#define NQB   (NPTS / QT)    // 16
#define NCB   (NPTS / CT)    // 16
#define GRPC  16             // row-deferral group (cands)
#define FLTMAX 3.402823466e38f

typedef unsigned long long u64;

// row partials per cand-block: (best value, group index as float)
__device__ float2 g_row[NCB][BATCH * NPTS];
// col partials: partial p covers queries [p*128, p*128+128) within the batch
__device__ float  g_col[NQB * 2][BATCH * NPTS];

__device__ __forceinline__ u64 pack2(float lo, float hi) {
    u64 r; asm("mov.b64 %0, {%1, %2};" : "=l"(r) : "f"(lo), "f"(hi)); return r;
}
__device__ __forceinline__ void unpack2(u64 v, float& lo, float& hi) {
    asm("mov.b64 {%0, %1}, %2;" : "=f"(lo), "=f"(hi) : "l"(v));
}
__device__ __forceinline__ u64 fma2(u64 a, u64 b, u64 c) {
    u64 d; asm("fma.rn.f32x2 %0, %1, %2, %3;" : "=l"(d) : "l"(a), "l"(b), "l"(c)); return d;
}
__device__ __forceinline__ u64 mul2(u64 a, u64 b) {
    u64 d; asm("mul.rn.f32x2 %0, %1, %2;" : "=l"(d) : "l"(a), "l"(b)); return d;
}
__device__ __forceinline__ u64 add2(u64 a, u64 b) {
    u64 d; asm("add.rn.f32x2 %0, %1, %2;" : "=l"(d) : "l"(a), "l"(b)); return d;
}

__device__ __forceinline__ float sqnorm_ref(float x, float y, float z) {
    return __fadd_rn(__fadd_rn(__fmul_rn(x, x), __fmul_rn(y, y)), __fmul_rn(z, z));
}
__device__ __forceinline__ float dist_ref(float qx, float qy, float qz, float q2,
                                          float cx, float cy, float cz, float c2) {
    float xy = __fmaf_rn(qz, cz, __fmaf_rn(qy, cy, __fmul_rn(qx, cx)));
    return __fmaf_rn(-2.0f, xy, __fadd_rn(q2, c2));
}

__global__ __launch_bounds__(BT) void nn_main(
    const float* __restrict__ xyz1,
    const float* __restrict__ xyz2)
{
    const int cblk = blockIdx.x, qblk = blockIdx.y, b = blockIdx.z;
    const int tid = threadIdx.x, w = tid >> 5, lane = tid & 31;

    __shared__ float4 sc[CT / 2][2];
    __shared__ u64 colpart[2][8][33];
    __shared__ float2 rowst[QT];

    // stage candidates (xyz2), scaled by -2; norms from UNSCALED coords
    const float* cbase = xyz2 + (size_t)(b * NPTS + cblk * CT) * 3;
    for (int pp = tid; pp < CT / 2; pp += BT) {
        const float* p0 = cbase + 6 * pp;
        const float a0 = p0[0], a1 = p0[1], a2 = p0[2];
        const float b0 = p0[3], b1 = p0[4], b2 = p0[5];
        const float w0 = sqnorm_ref(a0, a1, a2);
        const float w1 = sqnorm_ref(b0, b1, b2);
        sc[pp][0] = make_float4(-2.0f * a0, -2.0f * b0, -2.0f * a1, -2.0f * b1);
        sc[pp][1] = make_float4(-2.0f * a2, -2.0f * b2, w0, w1);
    }

    // queries: thread owns 4 CONSECUTIVE queries (12 contiguous floats)
    u64 qx2[UQ], qy2[UQ], qz2[UQ], q22[UQ];
    float best[UQ], gacc[UQ], jgrp[UQ];
    {
        const int q0 = b * NPTS + qblk * QT + tid * UQ;
        const float4* qv = (const float4*)(xyz1 + 3 * q0);
        const float4 v0 = qv[0], v1 = qv[1], v2 = qv[2];
        const float qs[UQ][3] = {{v0.x, v0.y, v0.z}, {v0.w, v1.x, v1.y},
                                 {v1.z, v1.w, v2.x}, {v2.y, v2.z, v2.w}};
#pragma unroll
        for (int u = 0; u < UQ; ++u) {
            const float x0 = qs[u][0], x1 = qs[u][1], x2v = qs[u][2];
            const float s = sqnorm_ref(x0, x1, x2v);
            qx2[u] = pack2(x0, x0);
            qy2[u] = pack2(x1, x1);
            qz2[u] = pack2(x2v, x2v);
            q22[u] = pack2(s, s);
            best[u] = FLTMAX;
            gacc[u] = FLTMAX;
            jgrp[u] = 0.0f;
        }
    }
    __syncthreads();

    const ulonglong2* __restrict__ sp = (const ulonglong2*)sc;
    float* __restrict__ gcol = &g_col[qblk * 2 + w][b * NPTS + cblk * CT];

    for (int k8 = 0; k8 < CT / 2; k8 += 8) {
#pragma unroll
        for (int j = 0; j < 8; ++j) {
            const int un = k8 + j;
            const ulonglong2 A  = sp[2 * un];      // (-2X pair, -2Y pair)
            const ulonglong2 Bv = sp[2 * un + 1];  // (-2Z pair,  W pair)
            float cl, ch;
#pragma unroll
            for (int u = 0; u < UQ; ++u) {
                u64 t = fma2(qz2[u], Bv.x, fma2(qy2[u], A.y, mul2(qx2[u], A.x)));
                u64 d = add2(t, add2(q22[u], Bv.y));   // == fma(-2,xy,q2+c2)
                float dlo, dhi; unpack2(d, dlo, dhi);
                gacc[u] = fminf(gacc[u], fminf(dlo, dhi));
                if (u == 0) { cl = dlo; ch = dhi; }
                else        { cl = fminf(cl, dlo); ch = fminf(ch, dhi); }
            }
            colpart[w][j][lane] = pack2(cl, ch);
        }

        // row group commit (16 cands/group), ascending -> strict <
        const float gidx = (float)(cblk * (CT / GRPC) + (k8 >> 3));
#pragma unroll
        for (int u = 0; u < UQ; ++u) {
            jgrp[u] = (gacc[u] < best[u]) ? gidx : jgrp[u];
            best[u] = fminf(best[u], gacc[u]);
            gacc[u] = FLTMAX;
        }

        // col flush: 16 reductions (8 pairs x 2 halves) over 32 lanes
        __syncwarp();
        {
            const int p = lane >> 2;
            const int s = (lane >> 1) & 1;
            const int h = lane & 1;
            const float* fb = (const float*)colpart[w][p];
            float v = fb[(s * 16) * 2 + h];
#pragma unroll
            for (int i = 1; i < 16; ++i)
                v = fminf(v, fb[(s * 16 + i) * 2 + h]);
            v = fminf(v, __shfl_xor_sync(0xffffffffu, v, 2));
            if (!(lane & 2))
                gcol[k8 * 2 + p * 2 + h] = v;
        }
        __syncwarp();
    }

    // row epilogue: stage to smem, write coalesced
#pragma unroll
    for (int u = 0; u < UQ; ++u)
        rowst[tid * UQ + u] = make_float2(best[u], jgrp[u]);
    __syncthreads();
    {
        const int base = b * NPTS + qblk * QT;
        float2* __restrict__ gr = &g_row[cblk][base];
        for (int i = tid; i < QT; i += BT) gr[i] = rowst[i];
    }
}

// Fused finalize: one WARP per output element. Warps [0, BN) do rows,
// warps [BN, 2*BN) do cols. All merges keep the EARLIEST tying partial and
// all rescans recompute distances bit-identically, taking the LOWEST matching
// index -> exact first-occurrence argmin.
__global__ __launch_bounds__(256) void nn_finalize(
    const float* __restrict__ xyz1,
    const float* __restrict__ xyz2,
    float* __restrict__ out)
{
    const int BN   = BATCH * NPTS;
    const int gw   = blockIdx.x * (blockDim.x >> 5) + (threadIdx.x >> 5);
    const int lane = threadIdx.x & 31;

    if (gw < BN) {
        // ---- row: dist1/idx1 for query qg ----
        const int qg = gw;
        const int b  = qg / NPTS;

        // lane cb (<NCB) owns partial cb: (value, group)
        float v = FLTMAX, g = 0.0f;
        int   p = 1 << 20;
        if (lane < NCB) {
            const float2 r = g_row[lane][qg];
            v = r.x; g = r.y; p = lane;
        }
#pragma unroll
        for (int off = 16; off >= 1; off >>= 1) {
            const float ov = __shfl_xor_sync(0xffffffffu, v, off);
            const float og = __shfl_xor_sync(0xffffffffu, g, off);
            const int   op = __shfl_xor_sync(0xffffffffu, p, off);
            const bool tk = (ov < v) || (ov == v && op < p);
            v = tk ? ov : v; g = tk ? og : g; p = tk ? op : p;
        }
        const float bv = v;
        const int base = (int)g * GRPC;

        const float* qp = xyz1 + 3 * qg;
        const float qx = qp[0], qy = qp[1], qz = qp[2];
        const float q2 = sqnorm_ref(qx, qy, qz);

        int found = 0x7fffffff;
        if (lane < GRPC) {
            const float* cp = xyz2 + (size_t)b * NPTS * 3 + 3 * (base + lane);
            const float c2 = sqnorm_ref(cp[0], cp[1], cp[2]);
            const float d = dist_ref(qx, qy, qz, q2, cp[0], cp[1], cp[2], c2);
            if (d == bv) found = base + lane;
        }
#pragma unroll
        for (int off = 16; off >= 1; off >>= 1)
            found = min(found, __shfl_xor_sync(0xffffffffu, found, off));

        if (lane == 0) {
            out[qg]          = bv;
            out[2 * BN + qg] = (float)found;
        }
    } else {
        // ---- col: dist2/idx2 for candidate mg ----
        const int mg = gw - BN;
        const int b  = mg / NPTS;

        // lane l owns partial l: contiguous queries [l*128, l*128+128)
        float v = g_col[lane][mg];
        int   p = lane;
#pragma unroll
        for (int off = 16; off >= 1; off >>= 1) {
            const float ov = __shfl_xor_sync(0xffffffffu, v, off);
            const int   op = __shfl_xor_sync(0xffffffffu, p, off);
            const bool tk = (ov < v) || (ov == v && op < p);
            v = tk ? ov : v; p = tk ? op : p;
        }
        const float bv = v;
        const int   bp = p;

        const float* cp = xyz2 + 3 * mg;
        const float cx = cp[0], cy = cp[1], cz = cp[2];
        const float c2 = sqnorm_ref(cx, cy, cz);

        // rescan: lane l -> queries bp*128 + l*4 + {0..3}, coalesced float4
        const int q0 = b * NPTS + bp * 128 + lane * 4;
        const float4* qv = (const float4*)(xyz1 + 3 * q0);
        const float4 v0 = qv[0], v1 = qv[1], v2 = qv[2];
        const float qs[4][3] = {{v0.x, v0.y, v0.z}, {v0.w, v1.x, v1.y},
                                {v1.z, v1.w, v2.x}, {v2.y, v2.z, v2.w}};
        int found = 0x7fffffff;
#pragma unroll
        for (int k = 3; k >= 0; --k) {
            const float q2n = sqnorm_ref(qs[k][0], qs[k][1], qs[k][2]);
            const float d = dist_ref(qs[k][0], qs[k][1], qs[k][2], q2n,
                                     cx, cy, cz, c2);
            if (d == bv) found = bp * 128 + lane * 4 + k;
        }
#pragma unroll
        for (int off = 16; off >= 1; off >>= 1)
            found = min(found, __shfl_xor_sync(0xffffffffu, found, off));

        if (lane == 0) {
            out[BN + mg]     = bv;
            out[3 * BN + mg] = (float)found;
        }
    }
}

extern "C" void kernel_launch(void* const* d_in, const int* in_sizes, int n_in,
                              void* d_out, int out_size)
{
    (void)in_sizes; (void)n_in; (void)out_size;
    const float* xyz1 = (const float*)d_in[0];
    const float* xyz2 = (const float*)d_in[1];
    float* out = (float*)d_out;

    dim3 grid(NCB, NQB, BATCH);   // (16, 16, 16) = 4096 blocks
    nn_main<<<grid, BT>>>(xyz1, xyz2);

    const int BN = BATCH * NPTS;
    nn_finalize<<<(2 * BN * 32) / 256, 256>>>(xyz1, xyz2, out);
}

// round 10
// speedup vs baseline: 2.5998x; 1.1293x over previous
#include <cuda_runtime.h>

// chamfer_3DDist: B=16, N=M=4096.
// Output (float32): [dist1 (B*N) | dist2 (B*M) | idx1 (B*N) | idx2 (B*M)]
//
// Round-10: finalize split into (A) coalesced thread-per-element merge and
// (B) lean warp-per-element rescan. R9's fused warp-per-element finalize had
// uncoalesced merge loads (32 sectors/warp) and ~150 warp-instrs per output
// element; now merge loads are fully coalesced and rescan is the only
// warp-cooperative part. Main kernel unchanged (at ~80% of its banked-FFMA2
// pipe floor). All distances and tie-break orders bit-identical to reference.

#define BT    64
#define UQ    4
#define QT    256            // queries per block (BT*UQ)
#define CT    256            // candidates per block
#define NPTS  4096
#define BATCH 16
#define NQB   (NPTS / QT)    // 16
#define NCB   (NPTS / CT)    // 16
#define GRPC  16             // row-deferral group (cands)
#define NPART (NQB * 2)      // 32 col partials (contiguous 128-query ranges)
#define FLTMAX 3.402823466e38f

typedef unsigned long long u64;

// row partials per cand-block: (best value, group index as float)
__device__ float2 g_row[NCB][BATCH * NPTS];
// col partials: partial p covers queries [p*128, p*128+128) within the batch
__device__ float  g_col[NPART][BATCH * NPTS];
// merge selections: [0]=row winning group, [1]=col winning partial
__device__ int    g_sel[2][BATCH * NPTS];

__device__ __forceinline__ u64 pack2(float lo, float hi) {
    u64 r; asm("mov.b64 %0, {%1, %2};" : "=l"(r) : "f"(lo), "f"(hi)); return r;
}
__device__ __forceinline__ void unpack2(u64 v, float& lo, float& hi) {
    asm("mov.b64 {%0, %1}, %2;" : "=f"(lo), "=f"(hi) : "l"(v));
}
__device__ __forceinline__ u64 fma2(u64 a, u64 b, u64 c) {
    u64 d; asm("fma.rn.f32x2 %0, %1, %2, %3;" : "=l"(d) : "l"(a), "l"(b), "l"(c)); return d;
}
__device__ __forceinline__ u64 mul2(u64 a, u64 b) {
    u64 d; asm("mul.rn.f32x2 %0, %1, %2;" : "=l"(d) : "l"(a), "l"(b)); return d;
}
__device__ __forceinline__ u64 add2(u64 a, u64 b) {
    u64 d; asm("add.rn.f32x2 %0, %1, %2;" : "=l"(d) : "l"(a), "l"(b)); return d;
}

__device__ __forceinline__ float sqnorm_ref(float x, float y, float z) {
    return __fadd_rn(__fadd_rn(__fmul_rn(x, x), __fmul_rn(y, y)), __fmul_rn(z, z));
}
__device__ __forceinline__ float dist_ref(float qx, float qy, float qz, float q2,
                                          float cx, float cy, float cz, float c2) {
    float xy = __fmaf_rn(qz, cz, __fmaf_rn(qy, cy, __fmul_rn(qx, cx)));
    return __fmaf_rn(-2.0f, xy, __fadd_rn(q2, c2));
}

__global__ __launch_bounds__(BT) void nn_main(
    const float* __restrict__ xyz1,
    const float* __restrict__ xyz2)
{
    const int cblk = blockIdx.x, qblk = blockIdx.y, b = blockIdx.z;
    const int tid = threadIdx.x, w = tid >> 5, lane = tid & 31;

    __shared__ float4 sc[CT / 2][2];
    __shared__ u64 colpart[2][8][33];
    __shared__ float2 rowst[QT];

    // stage candidates (xyz2), scaled by -2; norms from UNSCALED coords
    const float* cbase = xyz2 + (size_t)(b * NPTS + cblk * CT) * 3;
    for (int pp = tid; pp < CT / 2; pp += BT) {
        const float* p0 = cbase + 6 * pp;
        const float a0 = p0[0], a1 = p0[1], a2 = p0[2];
        const float b0 = p0[3], b1 = p0[4], b2 = p0[5];
        const float w0 = sqnorm_ref(a0, a1, a2);
        const float w1 = sqnorm_ref(b0, b1, b2);
        sc[pp][0] = make_float4(-2.0f * a0, -2.0f * b0, -2.0f * a1, -2.0f * b1);
        sc[pp][1] = make_float4(-2.0f * a2, -2.0f * b2, w0, w1);
    }

    // queries: thread owns 4 CONSECUTIVE queries (12 contiguous floats)
    u64 qx2[UQ], qy2[UQ], qz2[UQ], q22[UQ];
    float best[UQ], gacc[UQ], jgrp[UQ];
    {
        const int q0 = b * NPTS + qblk * QT + tid * UQ;
        const float4* qv = (const float4*)(xyz1 + 3 * q0);
        const float4 v0 = qv[0], v1 = qv[1], v2 = qv[2];
        const float qs[UQ][3] = {{v0.x, v0.y, v0.z}, {v0.w, v1.x, v1.y},
                                 {v1.z, v1.w, v2.x}, {v2.y, v2.z, v2.w}};
#pragma unroll
        for (int u = 0; u < UQ; ++u) {
            const float x0 = qs[u][0], x1 = qs[u][1], x2v = qs[u][2];
            const float s = sqnorm_ref(x0, x1, x2v);
            qx2[u] = pack2(x0, x0);
            qy2[u] = pack2(x1, x1);
            qz2[u] = pack2(x2v, x2v);
            q22[u] = pack2(s, s);
            best[u] = FLTMAX;
            gacc[u] = FLTMAX;
            jgrp[u] = 0.0f;
        }
    }
    __syncthreads();

    const ulonglong2* __restrict__ sp = (const ulonglong2*)sc;
    float* __restrict__ gcol = &g_col[qblk * 2 + w][b * NPTS + cblk * CT];

    for (int k8 = 0; k8 < CT / 2; k8 += 8) {
#pragma unroll
        for (int j = 0; j < 8; ++j) {
            const int un = k8 + j;
            const ulonglong2 A  = sp[2 * un];      // (-2X pair, -2Y pair)
            const ulonglong2 Bv = sp[2 * un + 1];  // (-2Z pair,  W pair)
            float cl, ch;
#pragma unroll
            for (int u = 0; u < UQ; ++u) {
                u64 t = fma2(qz2[u], Bv.x, fma2(qy2[u], A.y, mul2(qx2[u], A.x)));
                u64 d = add2(t, add2(q22[u], Bv.y));   // == fma(-2,xy,q2+c2)
                float dlo, dhi; unpack2(d, dlo, dhi);
                gacc[u] = fminf(gacc[u], fminf(dlo, dhi));
                if (u == 0) { cl = dlo; ch = dhi; }
                else        { cl = fminf(cl, dlo); ch = fminf(ch, dhi); }
            }
            colpart[w][j][lane] = pack2(cl, ch);
        }

        // row group commit (16 cands/group), ascending -> strict <
        const float gidx = (float)(cblk * (CT / GRPC) + (k8 >> 3));
#pragma unroll
        for (int u = 0; u < UQ; ++u) {
            jgrp[u] = (gacc[u] < best[u]) ? gidx : jgrp[u];
            best[u] = fminf(best[u], gacc[u]);
            gacc[u] = FLTMAX;
        }

        // col flush: 16 reductions (8 pairs x 2 halves) over 32 lanes
        __syncwarp();
        {
            const int p = lane >> 2;
            const int s = (lane >> 1) & 1;
            const int h = lane & 1;
            const float* fb = (const float*)colpart[w][p];
            float v = fb[(s * 16) * 2 + h];
#pragma unroll
            for (int i = 1; i < 16; ++i)
                v = fminf(v, fb[(s * 16 + i) * 2 + h]);
            v = fminf(v, __shfl_xor_sync(0xffffffffu, v, 2));
            if (!(lane & 2))
                gcol[k8 * 2 + p * 2 + h] = v;
        }
        __syncwarp();
    }

    // row epilogue: stage to smem, write coalesced
#pragma unroll
    for (int u = 0; u < UQ; ++u)
        rowst[tid * UQ + u] = make_float2(best[u], jgrp[u]);
    __syncthreads();
    {
        const int base = b * NPTS + qblk * QT;
        float2* __restrict__ gr = &g_row[cblk][base];
        for (int i = tid; i < QT; i += BT) gr[i] = rowst[i];
    }
}

// Phase A: thread-per-element merge, fully coalesced (consecutive threads ->
// consecutive elements; each partial row scanned in lockstep). Ascending scan
// with strict < keeps the EARLIEST tying partial (exact first-occurrence).
__global__ __launch_bounds__(256) void nn_merge(float* __restrict__ out)
{
    const int t  = blockIdx.x * blockDim.x + threadIdx.x;   // [0, 2*BN)
    const int BN = BATCH * NPTS;

    if (t < BN) {
        const int qg = t;
        float2 r = g_row[0][qg];
        float bv = r.x, bg = r.y;
#pragma unroll
        for (int cb = 1; cb < NCB; ++cb) {
            const float2 rr = g_row[cb][qg];
            const bool tk = rr.x < bv;
            bv = tk ? rr.x : bv;
            bg = tk ? rr.y : bg;
        }
        out[qg] = bv;
        g_sel[0][qg] = (int)bg;
    } else {
        const int mg = t - BN;
        float bv = g_col[0][mg];
        int   bp = 0;
#pragma unroll
        for (int p = 1; p < NPART; ++p) {
            const float v = g_col[p][mg];
            const bool tk = v < bv;
            bv = tk ? v : bv;
            bp = tk ? p : bp;
        }
        out[BN + mg] = bv;
        g_sel[1][mg] = bp;
    }
}

// Phase B: warp-per-element rescan. Recomputes distances bit-identically in
// the winning group/range and takes the LOWEST matching global index.
__global__ __launch_bounds__(256) void nn_rescan(
    const float* __restrict__ xyz1,
    const float* __restrict__ xyz2,
    float* __restrict__ out)
{
    const int BN   = BATCH * NPTS;
    const int gw   = blockIdx.x * (blockDim.x >> 5) + (threadIdx.x >> 5);
    const int lane = threadIdx.x & 31;

    if (gw < BN) {
        // row: idx1 for query qg
        const int qg = gw;
        const int b  = qg >> 12;            // /NPTS
        const float bv = out[qg];
        const int base = g_sel[0][qg] * GRPC;

        const float* qp = xyz1 + 3 * qg;
        const float qx = qp[0], qy = qp[1], qz = qp[2];
        const float q2 = sqnorm_ref(qx, qy, qz);

        int found = 0x7fffffff;
        if (lane < GRPC) {
            const float* cp = xyz2 + (size_t)b * NPTS * 3 + 3 * (base + lane);
            const float c2 = sqnorm_ref(cp[0], cp[1], cp[2]);
            const float d = dist_ref(qx, qy, qz, q2, cp[0], cp[1], cp[2], c2);
            if (d == bv) found = base + lane;
        }
#pragma unroll
        for (int off = 16; off >= 1; off >>= 1)
            found = min(found, __shfl_xor_sync(0xffffffffu, found, off));

        if (lane == 0) out[2 * BN + qg] = (float)found;
    } else {
        // col: idx2 for candidate mg
        const int mg = gw - BN;
        const int b  = mg >> 12;
        const float bv = out[BN + mg];
        const int   bp = g_sel[1][mg];      // queries [bp*128, bp*128+128)

        const float* cp = xyz2 + 3 * mg;
        const float cx = cp[0], cy = cp[1], cz = cp[2];
        const float c2 = sqnorm_ref(cx, cy, cz);

        const int q0 = b * NPTS + bp * 128 + lane * 4;
        const float4* qv = (const float4*)(xyz1 + 3 * q0);
        const float4 v0 = qv[0], v1 = qv[1], v2 = qv[2];
        const float qs[4][3] = {{v0.x, v0.y, v0.z}, {v0.w, v1.x, v1.y},
                                {v1.z, v1.w, v2.x}, {v2.y, v2.z, v2.w}};
        int found = 0x7fffffff;
#pragma unroll
        for (int k = 3; k >= 0; --k) {
            const float q2n = sqnorm_ref(qs[k][0], qs[k][1], qs[k][2]);
            const float d = dist_ref(qs[k][0], qs[k][1], qs[k][2], q2n,
                                     cx, cy, cz, c2);
            if (d == bv) found = bp * 128 + lane * 4 + k;
        }
#pragma unroll
        for (int off = 16; off >= 1; off >>= 1)
            found = min(found, __shfl_xor_sync(0xffffffffu, found, off));

        if (lane == 0) out[3 * BN + mg] = (float)found;
    }
}

extern "C" void kernel_launch(void* const* d_in, const int* in_sizes, int n_in,
                              void* d_out, int out_size)
{
    (void)in_sizes; (void)n_in; (void)out_size;
    const float* xyz1 = (const float*)d_in[0];
    const float* xyz2 = (const float*)d_in[1];
    float* out = (float*)d_out;

    dim3 grid(NCB, NQB, BATCH);   // (16, 16, 16) = 4096 blocks
    nn_main<<<grid, BT>>>(xyz1, xyz2);

    const int BN = BATCH * NPTS;
    nn_merge<<<(2 * BN) / 256, 256>>>(out);
    nn_rescan<<<(2 * BN * 32) / 256, 256>>>(xyz1, xyz2, out);
}